// round 1
// baseline (speedup 1.0000x reference)
#include <cuda_runtime.h>
#include <math.h>

// Hyperbolic_Lines: out = sum_i acosh(1 + d2_i)^2
// where d2_i = ||y_i||^2 - (y_i . w)^2 / ||w||^2
//
// Single streaming pass over y (256 MB) -> HBM-bound. One warp per row,
// lane l handles float4 at column 4l (512B coalesced per row).

#define NROWS 500000
#define DCOLS 128
#define THREADS_PER_BLOCK 256
#define WARPS_PER_BLOCK (THREADS_PER_BLOCK / 32)
#define GRID_BLOCKS 1184   // 148 SMs * 8 blocks

__global__ void hl_init_kernel(float* out) {
    out[0] = 0.0f;
}

__global__ __launch_bounds__(THREADS_PER_BLOCK, 8)
void hl_main_kernel(const float* __restrict__ w,
                    const float* __restrict__ y,
                    float* __restrict__ out,
                    int n_rows) {
    const int lane  = threadIdx.x & 31;
    const int warp  = threadIdx.x >> 5;
    const int gwarp = blockIdx.x * WARPS_PER_BLOCK + warp;
    const int total_warps = gridDim.x * WARPS_PER_BLOCK;

    // w: one float4 per lane, loaded once (lives in registers).
    const float4 w4 = reinterpret_cast<const float4*>(w)[lane];

    // ||w||^2 via butterfly reduce (all lanes get the result).
    float nw2 = w4.x * w4.x + w4.y * w4.y + w4.z * w4.z + w4.w * w4.w;
    #pragma unroll
    for (int off = 16; off > 0; off >>= 1)
        nw2 += __shfl_xor_sync(0xFFFFFFFFu, nw2, off);
    const float inv_nw2 = 1.0f / nw2;

    const float4* __restrict__ y4p = reinterpret_cast<const float4*>(y);

    float acc = 0.0f;  // per-thread partial of sum(acosh(1+d2)^2); only lane 0 adds

    // 2-row unrolled grid-stride loop over rows, one row per warp.
    int row = gwarp * 2;
    const int row_stride = total_warps * 2;
    for (; row + 1 < n_rows; row += row_stride) {
        // Batch both loads up front for MLP.
        const float4 a = y4p[(size_t)row * 32 + lane];
        const float4 b = y4p[(size_t)(row + 1) * 32 + lane];

        float s1a = a.x * a.x + a.y * a.y + a.z * a.z + a.w * a.w;
        float s2a = a.x * w4.x + a.y * w4.y + a.z * w4.z + a.w * w4.w;
        float s1b = b.x * b.x + b.y * b.y + b.z * b.z + b.w * b.w;
        float s2b = b.x * w4.x + b.y * w4.y + b.z * w4.z + b.w * w4.w;

        #pragma unroll
        for (int off = 16; off > 0; off >>= 1) {
            s1a += __shfl_xor_sync(0xFFFFFFFFu, s1a, off);
            s2a += __shfl_xor_sync(0xFFFFFFFFu, s2a, off);
            s1b += __shfl_xor_sync(0xFFFFFFFFu, s1b, off);
            s2b += __shfl_xor_sync(0xFFFFFFFFu, s2b, off);
        }

        if (lane == 0) {
            float d2a = s1a - s2a * s2a * inv_nw2;
            float d2b = s1b - s2b * s2b * inv_nw2;
            float xa = 1.0f + d2a;
            float xb = 1.0f + d2b;
            float ta = __logf(xa + sqrtf(xa * xa - 1.0f));
            float tb = __logf(xb + sqrtf(xb * xb - 1.0f));
            acc += ta * ta + tb * tb;
        }
    }
    // Tail (at most 1 row per warp).
    if (row < n_rows) {
        const float4 a = y4p[(size_t)row * 32 + lane];
        float s1a = a.x * a.x + a.y * a.y + a.z * a.z + a.w * a.w;
        float s2a = a.x * w4.x + a.y * w4.y + a.z * w4.z + a.w * w4.w;
        #pragma unroll
        for (int off = 16; off > 0; off >>= 1) {
            s1a += __shfl_xor_sync(0xFFFFFFFFu, s1a, off);
            s2a += __shfl_xor_sync(0xFFFFFFFFu, s2a, off);
        }
        if (lane == 0) {
            float d2a = s1a - s2a * s2a * inv_nw2;
            float xa = 1.0f + d2a;
            float ta = __logf(xa + sqrtf(xa * xa - 1.0f));
            acc += ta * ta;
        }
    }

    // Block reduction: lane 0 of each warp -> shared -> warp 0 -> one atomicAdd.
    __shared__ float warp_sums[WARPS_PER_BLOCK];
    if (lane == 0) warp_sums[warp] = acc;
    __syncthreads();

    if (warp == 0) {
        float v = (lane < WARPS_PER_BLOCK) ? warp_sums[lane] : 0.0f;
        #pragma unroll
        for (int off = 16; off > 0; off >>= 1)
            v += __shfl_xor_sync(0xFFFFFFFFu, v, off);
        if (lane == 0)
            atomicAdd(out, v);
    }
}

extern "C" void kernel_launch(void* const* d_in, const int* in_sizes, int n_in,
                              void* d_out, int out_size) {
    const float* w = (const float*)d_in[0];   // [128]
    const float* y = (const float*)d_in[1];   // [500000, 128]
    float* out = (float*)d_out;

    const int n_rows = in_sizes[1] / DCOLS;

    hl_init_kernel<<<1, 1>>>(out);
    hl_main_kernel<<<GRID_BLOCKS, THREADS_PER_BLOCK>>>(w, y, out, n_rows);
}

// round 5
// speedup vs baseline: 1.0529x; 1.0529x over previous
#include <cuda_runtime.h>
#include <math.h>

// Hyperbolic_Lines: out = sum_i acosh(1 + d2_i)^2
//   d2_i = ||y_i||^2 - (y_i . w)^2 / ||w||^2
//
// HBM-bound streaming reduction over y (256 MB).
// 8 lanes per row: sublane s covers float4 indices {s, s+8, s+16, s+24},
// so each LDG.128 instruction is 4 disjoint fully-coalesced 128B blocks
// (one per 8-lane row-group). Per-row reduction = 3 butterfly steps within
// the 8-lane group, amortized over 4 rows -> 0.75 SHFL/row (was 10/row in R1).
// 2x row-group unroll -> 8 independent LDG.128 batched per warp iteration.
// Fast path (n_rows % 8 == 0, true for N=500000): no per-row bounds checks.

#define DCOLS 128
#define THREADS_PER_BLOCK 256
#define WARPS_PER_BLOCK (THREADS_PER_BLOCK / 32)
#define GRID_BLOCKS 1184   // 148 SMs * 8 blocks

__global__ void hl_init_kernel(float* out) {
    out[0] = 0.0f;
}

__device__ __forceinline__ float dot4(float4 a, float4 b) {
    return a.x * b.x + a.y * b.y + a.z * b.z + a.w * b.w;
}

__global__ __launch_bounds__(THREADS_PER_BLOCK, 4)
void hl_main_kernel(const float* __restrict__ w,
                    const float* __restrict__ y,
                    float* __restrict__ out,
                    int n_rows) {
    const int lane = threadIdx.x & 31;
    const int sub  = lane & 7;    // position within 8-lane row-group
    const int grp  = lane >> 3;   // which of 4 rows this lane serves
    const int warp = threadIdx.x >> 5;
    const int gwarp = blockIdx.x * WARPS_PER_BLOCK + warp;
    const int total_warps = gridDim.x * WARPS_PER_BLOCK;

    const float4* __restrict__ w4p = reinterpret_cast<const float4*>(w);
    const float4* __restrict__ y4p = reinterpret_cast<const float4*>(y);

    // w chunk for this sublane: float4 indices sub + 8k (16 floats, in regs).
    float4 wv0 = w4p[sub + 0];
    float4 wv1 = w4p[sub + 8];
    float4 wv2 = w4p[sub + 16];
    float4 wv3 = w4p[sub + 24];

    // ||w||^2: partial over this lane's 16 elements, butterfly within group.
    float nw2 = dot4(wv0, wv0) + dot4(wv1, wv1) + dot4(wv2, wv2) + dot4(wv3, wv3);
    nw2 += __shfl_xor_sync(0xFFFFFFFFu, nw2, 1);
    nw2 += __shfl_xor_sync(0xFFFFFFFFu, nw2, 2);
    nw2 += __shfl_xor_sync(0xFFFFFFFFu, nw2, 4);
    const float inv_nw2 = 1.0f / nw2;

    float acc = 0.0f;  // real values only on sublane-0 lanes

    const int stride = total_warps * 8;
    const int n_full = n_rows & ~7;   // multiple of 8 (== n_rows for N=500000)

    // ---- Fast path: all 8 rows of the group in bounds, no predicates. ----
    for (int base = gwarp * 8; base + 8 <= n_full; base += stride) {
        const float4* pa = y4p + ((size_t)(base + grp)) * 32 + sub;
        const float4* pb = pa + 4 * 32;

        // Batch all 8 loads up front (MLP=8 per warp).
        float4 a0 = pa[0], a1 = pa[8], a2 = pa[16], a3 = pa[24];
        float4 b0 = pb[0], b1 = pb[8], b2 = pb[16], b3 = pb[24];

        float s1a = dot4(a0, a0) + dot4(a1, a1) + dot4(a2, a2) + dot4(a3, a3);
        float s2a = dot4(a0, wv0) + dot4(a1, wv1) + dot4(a2, wv2) + dot4(a3, wv3);
        float s1b = dot4(b0, b0) + dot4(b1, b1) + dot4(b2, b2) + dot4(b3, b3);
        float s2b = dot4(b0, wv0) + dot4(b1, wv1) + dot4(b2, wv2) + dot4(b3, wv3);

        #pragma unroll
        for (int off = 1; off <= 4; off <<= 1) {
            s1a += __shfl_xor_sync(0xFFFFFFFFu, s1a, off);
            s2a += __shfl_xor_sync(0xFFFFFFFFu, s2a, off);
            s1b += __shfl_xor_sync(0xFFFFFFFFu, s1b, off);
            s2b += __shfl_xor_sync(0xFFFFFFFFu, s2b, off);
        }

        if (sub == 0) {
            float d2a = s1a - s2a * s2a * inv_nw2;
            float d2b = s1b - s2b * s2b * inv_nw2;
            float xa = 1.0f + d2a;
            float xb = 1.0f + d2b;
            float ta = __logf(xa + sqrtf(xa * xa - 1.0f));
            float tb = __logf(xb + sqrtf(xb * xb - 1.0f));
            acc += ta * ta + tb * tb;
        }
    }

    // ---- Tail: remaining rows (none for N=500000). ----
    if (n_full < n_rows) {
        if (gwarp == 0) {
            for (int base = n_full; base < n_rows; base += 4) {
                const int r = base + grp;
                float s1 = 0.0f, s2 = 0.0f;
                if (r < n_rows) {
                    const float4* p = y4p + (size_t)r * 32 + sub;
                    float4 a0 = p[0], a1 = p[8], a2 = p[16], a3 = p[24];
                    s1 = dot4(a0, a0) + dot4(a1, a1) + dot4(a2, a2) + dot4(a3, a3);
                    s2 = dot4(a0, wv0) + dot4(a1, wv1) + dot4(a2, wv2) + dot4(a3, wv3);
                }
                #pragma unroll
                for (int off = 1; off <= 4; off <<= 1) {
                    s1 += __shfl_xor_sync(0xFFFFFFFFu, s1, off);
                    s2 += __shfl_xor_sync(0xFFFFFFFFu, s2, off);
                }
                if (sub == 0 && r < n_rows) {
                    float d2 = s1 - s2 * s2 * inv_nw2;
                    float x = 1.0f + d2;
                    float t = __logf(x + sqrtf(x * x - 1.0f));
                    acc += t * t;
                }
            }
        }
    }

    // Warp reduce acc, then block reduce, one atomicAdd per block.
    #pragma unroll
    for (int off = 16; off > 0; off >>= 1)
        acc += __shfl_xor_sync(0xFFFFFFFFu, acc, off);

    __shared__ float warp_sums[WARPS_PER_BLOCK];
    if (lane == 0) warp_sums[warp] = acc;
    __syncthreads();

    if (warp == 0) {
        float v = (lane < WARPS_PER_BLOCK) ? warp_sums[lane] : 0.0f;
        #pragma unroll
        for (int off = 16; off > 0; off >>= 1)
            v += __shfl_xor_sync(0xFFFFFFFFu, v, off);
        if (lane == 0)
            atomicAdd(out, v);
    }
}

extern "C" void kernel_launch(void* const* d_in, const int* in_sizes, int n_in,
                              void* d_out, int out_size) {
    const float* w = (const float*)d_in[0];   // [128]
    const float* y = (const float*)d_in[1];   // [500000, 128]
    float* out = (float*)d_out;

    const int n_rows = in_sizes[1] / DCOLS;

    hl_init_kernel<<<1, 1>>>(out);
    hl_main_kernel<<<GRID_BLOCKS, THREADS_PER_BLOCK>>>(w, y, out, n_rows);
}